// round 2
// baseline (speedup 1.0000x reference)
#include <cuda_runtime.h>
#include <cstdint>
#include <cstddef>

// Problem dims
constexpr int kB  = 16;    // batch
constexpr int kN  = 512;   // num inputs
constexpr int kU  = 512;   // num units
constexpr int kT  = 1024;  // time = H*H
constexpr int kH  = 32;    // heads
constexpr int kCB = 512;   // C*B = (T/H)*B
constexpr float kNEG  = -4294967296.0f;  // float32(-2^32+1) rounds to -2^32
constexpr float kKEEP = 0.9f;

constexpr int    kNN     = kN * kN;                 // 262144
constexpr size_t kPSZ    = (size_t)kCB * kNN;       // 134217728 elems (512 MB)
constexpr int    kOUTSZ  = kH * kN * kB * kH;       // 8388608
constexpr int    kATTSZ  = kCB * kN;                // 262144

// Scratch (allocation-free contract: __device__ globals)
__device__ float g_Q[(size_t)kCB * kN * kH];
__device__ float g_K[(size_t)kCB * kN * kH];
__device__ float g_V[(size_t)kCB * kN * kH];
__device__ float g_P[kPSZ];          // scores, then dropped probs (512 MB)
__device__ float g_mx[kNN];
__device__ float g_sm[kNN];

// ---------------- threefry2x32 (exact JAX PRNG, partitionable layout) ----------------
// jax_threefry_partitionable=True (default since jax 0.4.30):
//   element i (< 2^32): x0 = 0, x1 = i, bits = out0 ^ out1
__device__ __forceinline__ void tf_round(uint32_t& a, uint32_t& b, int r) {
    a += b;
    b = (b << r) | (b >> (32 - r));
    b ^= a;
}
__device__ __forceinline__ void threefry(uint32_t k0, uint32_t k1,
                                         uint32_t& x0, uint32_t& x1) {
    uint32_t k2 = k0 ^ k1 ^ 0x1BD11BDAu;
    x0 += k0; x1 += k1;
    tf_round(x0,x1,13); tf_round(x0,x1,15); tf_round(x0,x1,26); tf_round(x0,x1,6);
    x0 += k1; x1 += k2 + 1u;
    tf_round(x0,x1,17); tf_round(x0,x1,29); tf_round(x0,x1,16); tf_round(x0,x1,24);
    x0 += k2; x1 += k0 + 2u;
    tf_round(x0,x1,13); tf_round(x0,x1,15); tf_round(x0,x1,26); tf_round(x0,x1,6);
    x0 += k0; x1 += k1 + 3u;
    tf_round(x0,x1,17); tf_round(x0,x1,29); tf_round(x0,x1,16); tf_round(x0,x1,24);
    x0 += k1; x1 += k2 + 4u;
    tf_round(x0,x1,13); tf_round(x0,x1,15); tf_round(x0,x1,26); tf_round(x0,x1,6);
    x0 += k2; x1 += k0 + 5u;
}
__device__ __forceinline__ uint32_t rng_bits(uint32_t k1, uint32_t idx) {
    uint32_t x0 = 0u, x1 = idx;
    threefry(0u, k1, x0, x1);
    return x0 ^ x1;
}
__device__ __forceinline__ bool keep_bit(uint32_t bits) {
    // jax.random.uniform: bitcast(bits>>9 | 0x3f800000) - 1.0 ; keep if < 0.9f
    float u = __uint_as_float((bits >> 9) | 0x3f800000u) - 1.0f;
    return u < kKEEP;
}

// ---------------- K1: projections, write in head layout [cb][n][h] ----------------
// Qx[b,n,t] = sum_u W[n,u] * x[b,u,t];  head layout: cb = (t>>5)*16 + b, h = t&31
__global__ void proj_kernel(const float* __restrict__ x,
                            const float* __restrict__ Qp,
                            const float* __restrict__ Kp,
                            const float* __restrict__ Vp) {
    int z = blockIdx.z;                 // mat*16 + b
    int mat = z >> 4, b = z & 15;
    const float* W  = (mat == 0) ? Qp : ((mat == 1) ? Kp : Vp);
    float* Out      = (mat == 0) ? g_Q : ((mat == 1) ? g_K : g_V);
    const float* X  = x + (size_t)b * kU * kT;

    int n0 = blockIdx.y * 128;
    int t0 = blockIdx.x * 64;

    __shared__ float As[16][128];       // [k][n]
    __shared__ float Bs[16][64];        // [k][t]

    int tid = threadIdx.x;              // 256 threads
    int tx = tid & 15;                  // t group (4 cols)
    int ty = tid >> 4;                  // n group (8 rows)

    float acc[8][4];
#pragma unroll
    for (int i = 0; i < 8; i++)
#pragma unroll
        for (int j = 0; j < 4; j++) acc[i][j] = 0.0f;

    for (int k0 = 0; k0 < kU; k0 += 16) {
#pragma unroll
        for (int i = 0; i < 8; i++) {   // A: 128x16
            int l = tid + i * 256;
            int r = l >> 4, k = l & 15;
            As[k][r] = W[(size_t)(n0 + r) * kU + k0 + k];
        }
#pragma unroll
        for (int i = 0; i < 4; i++) {   // B: 16x64
            int l = tid + i * 256;
            int k = l >> 6, t = l & 63;
            Bs[k][t] = X[(size_t)(k0 + k) * kT + t0 + t];
        }
        __syncthreads();
#pragma unroll
        for (int k = 0; k < 16; k++) {
            float a[8], bb[4];
#pragma unroll
            for (int i = 0; i < 8; i++) a[i] = As[k][ty * 8 + i];
#pragma unroll
            for (int j = 0; j < 4; j++) bb[j] = Bs[k][tx * 4 + j];
#pragma unroll
            for (int i = 0; i < 8; i++)
#pragma unroll
                for (int j = 0; j < 4; j++) acc[i][j] += a[i] * bb[j];
        }
        __syncthreads();
    }
#pragma unroll
    for (int i = 0; i < 8; i++) {
        int n = n0 + ty * 8 + i;
#pragma unroll
        for (int j = 0; j < 4; j++) {
            int t = t0 + tx * 4 + j;
            int c = t >> 5, h = t & 31;
            Out[((size_t)(c * 16 + b) * kN + n) * kH + h] = acc[i][j];
        }
    }
}

// ---------------- K2: scores[cb,n,m] = Qh.Kh^T with key mask ----------------
__global__ void scores_kernel(const int* __restrict__ pm) {
    int cb = blockIdx.z;
    int bb = cb & 15;
    int m0 = blockIdx.x * 64, n0 = blockIdx.y * 64;
    const float* Q = g_Q + (size_t)cb * kN * kH;
    const float* K = g_K + (size_t)cb * kN * kH;

    __shared__ float Qs[64][33];
    __shared__ float Ks[64][33];

    int tid = threadIdx.x;              // 256
#pragma unroll
    for (int i = 0; i < 8; i++) {
        int l = tid + i * 256;
        int r = l >> 5, h = l & 31;
        Qs[r][h] = Q[(size_t)(n0 + r) * kH + h];
        Ks[r][h] = K[(size_t)(m0 + r) * kH + h];
    }
    __syncthreads();

    int tx = tid & 15, ty = tid >> 4;
    float acc[4][4];
#pragma unroll
    for (int i = 0; i < 4; i++)
#pragma unroll
        for (int j = 0; j < 4; j++) acc[i][j] = 0.0f;

#pragma unroll
    for (int h = 0; h < 32; h++) {
        float a[4], bq[4];
#pragma unroll
        for (int i = 0; i < 4; i++) a[i]  = Qs[ty * 4 + i][h];
#pragma unroll
        for (int j = 0; j < 4; j++) bq[j] = Ks[tx * 4 + j][h];
#pragma unroll
        for (int i = 0; i < 4; i++)
#pragma unroll
            for (int j = 0; j < 4; j++) acc[i][j] += a[i] * bq[j];
    }

#pragma unroll
    for (int i = 0; i < 4; i++) {
        int n = n0 + ty * 4 + i;
#pragma unroll
        for (int j = 0; j < 4; j++) {
            int m = m0 + tx * 4 + j;
            float v = (pm[bb * kN + m] == 0) ? kNEG : acc[i][j];
            g_P[((size_t)cb * kN + n) * kN + m] = v;
        }
    }
}

// ---------------- K3: online max & sumexp over axis 0 (cb) per (n,m) ----------------
__global__ void maxsum_kernel() {
    int idx = blockIdx.x * blockDim.x + threadIdx.x;  // 0..N*N-1
    const float* p = g_P + idx;
    float mx = __int_as_float(0xff800000);            // -inf
    float s = 0.0f;
    for (int cb = 0; cb < kCB; cb += 8) {
        float v[8];
#pragma unroll
        for (int u = 0; u < 8; u++) v[u] = p[(size_t)(cb + u) * kNN];
#pragma unroll
        for (int u = 0; u < 8; u++) {
            float vv = v[u];
            if (vv > mx) { s = s * __expf(mx - vv) + 1.0f; mx = vv; }
            else         { s += __expf(vv - mx); }
        }
    }
    g_mx[idx] = mx;
    g_sm[idx] = s;
}

// ---------------- K3b: probs = dropout(exp(s-mx)/sum), in place, exact JAX bits ----
__global__ void probsdrop_kernel() {
    uint32_t i = blockIdx.x * blockDim.x + threadIdx.x;  // 0..kPSZ-1
    uint32_t bits = rng_bits(1u, i);                     // key = jax.random.key(1)

    int nm = i & (kNN - 1);                              // kPSZ stride is multiple of kNN
    float mx = g_mx[nm];
    float sm = g_sm[nm];

    float v = g_P[i];
    float pr = __expf(v - mx) / sm;
    g_P[i] = keep_bit(bits) ? pr / kKEEP : 0.0f;
}

// ---------------- K4: ctx = probs @ Vh; epilogue: final layout + output dropout ----
__global__ void ctx_kernel(float* __restrict__ out) {
    int cb = blockIdx.y;
    int n0 = blockIdx.x * 128;
    const float* P = g_P + (size_t)cb * kNN;
    const float* V = g_V + (size_t)cb * kN * kH;

    __shared__ float Pst[64][129];              // [m][n], padded (conflict-free)
    __shared__ __align__(16) float Vs[64][32];  // [m][h]

    int tid = threadIdx.x;                      // 256
    int tx = tid & 7;                           // h group (4 cols)
    int ty = tid >> 3;                          // n group (4 rows), 0..31

    float acc[4][4];
#pragma unroll
    for (int i = 0; i < 4; i++)
#pragma unroll
        for (int j = 0; j < 4; j++) acc[i][j] = 0.0f;

    for (int m0 = 0; m0 < kN; m0 += 64) {
        for (int i = 0; i < 32; i++) {          // P tile: 128 n x 64 m, stored transposed
            int l = tid + i * 256;
            int r = l >> 6, ml = l & 63;
            Pst[ml][r] = P[(size_t)(n0 + r) * kN + m0 + ml];
        }
#pragma unroll
        for (int i = 0; i < 8; i++) {           // V tile: 64 m x 32 h
            int l = tid + i * 256;
            int k = l >> 5, h = l & 31;
            Vs[k][h] = V[(size_t)(m0 + k) * kH + h];
        }
        __syncthreads();
#pragma unroll
        for (int k = 0; k < 64; k++) {
            float4 v4 = *(const float4*)(&Vs[k][tx * 4]);
            float p0 = Pst[k][ty * 4 + 0];
            float p1 = Pst[k][ty * 4 + 1];
            float p2 = Pst[k][ty * 4 + 2];
            float p3 = Pst[k][ty * 4 + 3];
            acc[0][0] += p0 * v4.x; acc[0][1] += p0 * v4.y; acc[0][2] += p0 * v4.z; acc[0][3] += p0 * v4.w;
            acc[1][0] += p1 * v4.x; acc[1][1] += p1 * v4.y; acc[1][2] += p1 * v4.z; acc[1][3] += p1 * v4.w;
            acc[2][0] += p2 * v4.x; acc[2][1] += p2 * v4.y; acc[2][2] += p2 * v4.z; acc[2][3] += p2 * v4.w;
            acc[3][0] += p3 * v4.x; acc[3][1] += p3 * v4.y; acc[3][2] += p3 * v4.z; acc[3][3] += p3 * v4.w;
        }
        __syncthreads();
    }

    // out[j, n, i*32+h] with cb = i*32+j ; flat = (cb&31)*N*B*H + n*B*H + (cb>>5)*32 + h
    int jpart = (cb & 31) * (kN * kB * kH) + (cb >> 5) * kH;
#pragma unroll
    for (int i = 0; i < 4; i++) {
        int n = n0 + ty * 4 + i;
#pragma unroll
        for (int j = 0; j < 4; j++) {
            int h = tx * 4 + j;
            int oidx = jpart + n * (kB * kH) + h;
            uint32_t bits = rng_bits(2u, (uint32_t)oidx);  // key = jax.random.key(2)
            out[oidx] = keep_bit(bits) ? acc[i][j] / kKEEP : 0.0f;
        }
    }
}

// ---------------- K5: attention = probs[:, N-1, :] reshaped -> [B,H,N] ----------------
// att_flat[cb*512 + n] = probs[cb][511][n] (post-dropout), written after out block.
__global__ void attn_kernel(float* __restrict__ out) {
    int idx = blockIdx.x * blockDim.x + threadIdx.x;  // 0..kATTSZ-1
    int cb = idx >> 9, n = idx & 511;
    out[kOUTSZ + idx] = g_P[((size_t)cb * kN + (kN - 1)) * kN + n];
}

extern "C" void kernel_launch(void* const* d_in, const int* in_sizes, int n_in,
                              void* d_out, int out_size) {
    const float* x  = (const float*)d_in[0];
    const float* Qp = (const float*)d_in[1];
    const float* Kp = (const float*)d_in[2];
    const float* Vp = (const float*)d_in[3];
    const int*   pm = (const int*)d_in[4];
    float* out = (float*)d_out;

    proj_kernel  <<<dim3(kT / 64, kN / 128, 48), 256>>>(x, Qp, Kp, Vp);
    scores_kernel<<<dim3(kN / 64, kN / 64, kCB), 256>>>(pm);
    maxsum_kernel<<<kNN / 256, 256>>>();
    probsdrop_kernel<<<(int)(kPSZ / 256), 256>>>();
    ctx_kernel   <<<dim3(kN / 128, kCB), 256>>>(out);
    if (out_size >= kOUTSZ + kATTSZ) {
        attn_kernel<<<kATTSZ / 256, 256>>>(out);
    }
}

// round 3
// speedup vs baseline: 1.1983x; 1.1983x over previous
#include <cuda_runtime.h>
#include <cstdint>
#include <cstddef>

// Problem dims
constexpr int kB  = 16;    // batch
constexpr int kN  = 512;   // num inputs
constexpr int kU  = 512;   // num units
constexpr int kT  = 1024;  // time = H*H
constexpr int kH  = 32;    // heads
constexpr int kCB = 512;   // C*B = (T/H)*B
constexpr float kNEG  = -4294967296.0f;  // float32(-2^32+1) rounds to -2^32
constexpr float kKEEP = 0.9f;
constexpr float kRKEEP = 1.0f / 0.9f;

constexpr int    kNN     = kN * kN;                 // 262144
constexpr size_t kPSZ    = (size_t)kCB * kNN;       // 134217728 elems (512 MB)
constexpr int    kOUTSZ  = kH * kN * kB * kH;       // 8388608
constexpr int    kATTSZ  = kCB * kN;                // 262144

// Scratch (allocation-free contract: __device__ globals)
__device__ float g_Q[(size_t)kCB * kN * kH];
__device__ float g_K[(size_t)kCB * kN * kH];
__device__ float g_V[(size_t)kCB * kN * kH];
__device__ float g_P[kPSZ];          // raw (masked) scores only — probs never materialized
__device__ float g_mx[kNN];
__device__ float g_sminv[kNN];       // 1 / (0.9 * sum_exp)

// ---------------- threefry2x32 (exact JAX PRNG, partitionable layout) ----------------
// jax_threefry_partitionable=True: element i (< 2^32): x0 = 0, x1 = i, bits = out0 ^ out1
__device__ __forceinline__ void tf_round(uint32_t& a, uint32_t& b, int r) {
    a += b;
    b = __funnelshift_l(b, b, r);
    b ^= a;
}
__device__ __forceinline__ void threefry(uint32_t k0, uint32_t k1,
                                         uint32_t& x0, uint32_t& x1) {
    uint32_t k2 = k0 ^ k1 ^ 0x1BD11BDAu;
    x0 += k0; x1 += k1;
    tf_round(x0,x1,13); tf_round(x0,x1,15); tf_round(x0,x1,26); tf_round(x0,x1,6);
    x0 += k1; x1 += k2 + 1u;
    tf_round(x0,x1,17); tf_round(x0,x1,29); tf_round(x0,x1,16); tf_round(x0,x1,24);
    x0 += k2; x1 += k0 + 2u;
    tf_round(x0,x1,13); tf_round(x0,x1,15); tf_round(x0,x1,26); tf_round(x0,x1,6);
    x0 += k0; x1 += k1 + 3u;
    tf_round(x0,x1,17); tf_round(x0,x1,29); tf_round(x0,x1,16); tf_round(x0,x1,24);
    x0 += k1; x1 += k2 + 4u;
    tf_round(x0,x1,13); tf_round(x0,x1,15); tf_round(x0,x1,26); tf_round(x0,x1,6);
    x0 += k2; x1 += k0 + 5u;
}
__device__ __forceinline__ uint32_t rng_bits(uint32_t k1, uint32_t idx) {
    uint32_t x0 = 0u, x1 = idx;
    threefry(0u, k1, x0, x1);
    return x0 ^ x1;
}
__device__ __forceinline__ bool keep_bit(uint32_t bits) {
    float u = __uint_as_float((bits >> 9) | 0x3f800000u) - 1.0f;
    return u < kKEEP;
}

// ---------------- K1: projections, write in head layout [cb][n][h] ----------------
__global__ void proj_kernel(const float* __restrict__ x,
                            const float* __restrict__ Qp,
                            const float* __restrict__ Kp,
                            const float* __restrict__ Vp) {
    int z = blockIdx.z;                 // mat*16 + b
    int mat = z >> 4, b = z & 15;
    const float* W  = (mat == 0) ? Qp : ((mat == 1) ? Kp : Vp);
    float* Out      = (mat == 0) ? g_Q : ((mat == 1) ? g_K : g_V);
    const float* X  = x + (size_t)b * kU * kT;

    int n0 = blockIdx.y * 128;
    int t0 = blockIdx.x * 64;

    __shared__ float As[16][128];       // [k][n]
    __shared__ float Bs[16][64];        // [k][t]

    int tid = threadIdx.x;              // 256 threads
    int tx = tid & 15;                  // t group (4 cols)
    int ty = tid >> 4;                  // n group (8 rows)

    float acc[8][4];
#pragma unroll
    for (int i = 0; i < 8; i++)
#pragma unroll
        for (int j = 0; j < 4; j++) acc[i][j] = 0.0f;

    for (int k0 = 0; k0 < kU; k0 += 16) {
#pragma unroll
        for (int i = 0; i < 8; i++) {   // A: 128x16
            int l = tid + i * 256;
            int r = l >> 4, k = l & 15;
            As[k][r] = W[(size_t)(n0 + r) * kU + k0 + k];
        }
#pragma unroll
        for (int i = 0; i < 4; i++) {   // B: 16x64
            int l = tid + i * 256;
            int k = l >> 6, t = l & 63;
            Bs[k][t] = X[(size_t)(k0 + k) * kT + t0 + t];
        }
        __syncthreads();
#pragma unroll
        for (int k = 0; k < 16; k++) {
            float a[8], bb[4];
#pragma unroll
            for (int i = 0; i < 8; i++) a[i] = As[k][ty * 8 + i];
#pragma unroll
            for (int j = 0; j < 4; j++) bb[j] = Bs[k][tx * 4 + j];
#pragma unroll
            for (int i = 0; i < 8; i++)
#pragma unroll
                for (int j = 0; j < 4; j++) acc[i][j] += a[i] * bb[j];
        }
        __syncthreads();
    }
#pragma unroll
    for (int i = 0; i < 8; i++) {
        int n = n0 + ty * 8 + i;
#pragma unroll
        for (int j = 0; j < 4; j++) {
            int t = t0 + tx * 4 + j;
            int c = t >> 5, h = t & 31;
            Out[((size_t)(c * 16 + b) * kN + n) * kH + h] = acc[i][j];
        }
    }
}

// ---------------- K2: scores[cb,n,m] = Qh.Kh^T with key mask ----------------
__global__ void scores_kernel(const int* __restrict__ pm) {
    int cb = blockIdx.z;
    int bb = cb & 15;
    int m0 = blockIdx.x * 64, n0 = blockIdx.y * 64;
    const float* Q = g_Q + (size_t)cb * kN * kH;
    const float* K = g_K + (size_t)cb * kN * kH;

    __shared__ float Qs[64][33];
    __shared__ float Ks[64][33];

    int tid = threadIdx.x;              // 256
#pragma unroll
    for (int i = 0; i < 8; i++) {
        int l = tid + i * 256;
        int r = l >> 5, h = l & 31;
        Qs[r][h] = Q[(size_t)(n0 + r) * kH + h];
        Ks[r][h] = K[(size_t)(m0 + r) * kH + h];
    }
    __syncthreads();

    int tx = tid & 15, ty = tid >> 4;
    float acc[4][4];
#pragma unroll
    for (int i = 0; i < 4; i++)
#pragma unroll
        for (int j = 0; j < 4; j++) acc[i][j] = 0.0f;

#pragma unroll
    for (int h = 0; h < 32; h++) {
        float a[4], bq[4];
#pragma unroll
        for (int i = 0; i < 4; i++) a[i]  = Qs[ty * 4 + i][h];
#pragma unroll
        for (int j = 0; j < 4; j++) bq[j] = Ks[tx * 4 + j][h];
#pragma unroll
        for (int i = 0; i < 4; i++)
#pragma unroll
            for (int j = 0; j < 4; j++) acc[i][j] += a[i] * bq[j];
    }

#pragma unroll
    for (int i = 0; i < 4; i++) {
        int n = n0 + ty * 4 + i;
#pragma unroll
        for (int j = 0; j < 4; j++) {
            int m = m0 + tx * 4 + j;
            float v = (pm[bb * kN + m] == 0) ? kNEG : acc[i][j];
            g_P[((size_t)cb * kN + n) * kN + m] = v;
        }
    }
}

// ---------------- K3: online max & sumexp over axis 0 (cb); store 1/(0.9*sum) ------
__global__ void maxsum_kernel() {
    int idx = blockIdx.x * blockDim.x + threadIdx.x;  // 0..N*N-1
    const float* p = g_P + idx;
    float mx = __int_as_float(0xff800000);            // -inf
    float s = 0.0f;
    for (int cb = 0; cb < kCB; cb += 8) {
        float v[8];
#pragma unroll
        for (int u = 0; u < 8; u++) v[u] = p[(size_t)(cb + u) * kNN];
#pragma unroll
        for (int u = 0; u < 8; u++) {
            float vv = v[u];
            if (vv > mx) { s = s * __expf(mx - vv) + 1.0f; mx = vv; }
            else         { s += __expf(vv - mx); }
        }
    }
    g_mx[idx] = mx;
    g_sminv[idx] = 1.0f / (kKEEP * s);
}

// ---------------- K4: ctx = dropout(softmax(scores)) @ Vh, fully fused ------------
// P-tile load applies softmax normalize + exact-bit dropout on the fly.
__global__ void ctx_kernel(float* __restrict__ out) {
    int cb = blockIdx.y;
    int n0 = blockIdx.x * 128;
    const float* Praw = g_P + (size_t)cb * kNN;
    const float* V = g_V + (size_t)cb * kN * kH;

    __shared__ float Pst[64][129];              // [m][n], padded
    __shared__ __align__(16) float Vs[64][32];  // [m][h]

    int tid = threadIdx.x;                      // 256
    int tx = tid & 7;                           // h group (4 cols)
    int ty = tid >> 3;                          // n group (4 rows)

    float acc[4][4];
#pragma unroll
    for (int i = 0; i < 4; i++)
#pragma unroll
        for (int j = 0; j < 4; j++) acc[i][j] = 0.0f;

    int ml  = tid & 63;                         // fixed m within tile per thread
    int rb  = tid >> 6;                         // row base 0..3

    for (int m0 = 0; m0 < kN; m0 += 64) {
        // P tile: 128 n x 64 m; softmax + dropout fused
#pragma unroll
        for (int i = 0; i < 32; i++) {
            int r = rb + i * 4;                 // n row 0..127
            int n = n0 + r;
            int m = m0 + ml;
            int nm = n * kN + m;
            uint32_t gi = (uint32_t)(((size_t)cb * kN + n) * kN + m);
            float v = Praw[(size_t)n * kN + m];
            float pr = __expf(v - g_mx[nm]) * g_sminv[nm];
            uint32_t bits = rng_bits(1u, gi);   // key = jax.random.key(1)
            Pst[ml][r] = keep_bit(bits) ? pr : 0.0f;
        }
#pragma unroll
        for (int i = 0; i < 8; i++) {           // V tile: 64 m x 32 h
            int l = tid + i * 256;
            int k = l >> 5, h = l & 31;
            Vs[k][h] = V[(size_t)(m0 + k) * kH + h];
        }
        __syncthreads();
#pragma unroll
        for (int k = 0; k < 64; k++) {
            float4 v4 = *(const float4*)(&Vs[k][tx * 4]);
            float p0 = Pst[k][ty * 4 + 0];
            float p1 = Pst[k][ty * 4 + 1];
            float p2 = Pst[k][ty * 4 + 2];
            float p3 = Pst[k][ty * 4 + 3];
            acc[0][0] += p0 * v4.x; acc[0][1] += p0 * v4.y; acc[0][2] += p0 * v4.z; acc[0][3] += p0 * v4.w;
            acc[1][0] += p1 * v4.x; acc[1][1] += p1 * v4.y; acc[1][2] += p1 * v4.z; acc[1][3] += p1 * v4.w;
            acc[2][0] += p2 * v4.x; acc[2][1] += p2 * v4.y; acc[2][2] += p2 * v4.z; acc[2][3] += p2 * v4.w;
            acc[3][0] += p3 * v4.x; acc[3][1] += p3 * v4.y; acc[3][2] += p3 * v4.z; acc[3][3] += p3 * v4.w;
        }
        __syncthreads();
    }

    // out[j, n, i*32+h] with cb = i*32+j
    int jpart = (cb & 31) * (kN * kB * kH) + (cb >> 5) * kH;
#pragma unroll
    for (int i = 0; i < 4; i++) {
        int n = n0 + ty * 4 + i;
#pragma unroll
        for (int j = 0; j < 4; j++) {
            int h = tx * 4 + j;
            int oidx = jpart + n * (kB * kH) + h;
            uint32_t bits = rng_bits(2u, (uint32_t)oidx);  // key = jax.random.key(2)
            out[oidx] = keep_bit(bits) ? acc[i][j] * kRKEEP : 0.0f;
        }
    }
}

// ---------------- K5: attention = dropout(probs)[:, N-1, :] recomputed ------------
__global__ void attn_kernel(float* __restrict__ out) {
    int idx = blockIdx.x * blockDim.x + threadIdx.x;  // 0..kATTSZ-1
    int cb = idx >> 9, m = idx & 511;
    uint32_t gi = (uint32_t)(((size_t)cb * kN + (kN - 1)) * kN + m);
    int nm = (kN - 1) * kN + m;
    float v = g_P[gi];
    float pr = __expf(v - g_mx[nm]) * g_sminv[nm];
    uint32_t bits = rng_bits(1u, gi);
    out[kOUTSZ + idx] = keep_bit(bits) ? pr : 0.0f;
}

extern "C" void kernel_launch(void* const* d_in, const int* in_sizes, int n_in,
                              void* d_out, int out_size) {
    const float* x  = (const float*)d_in[0];
    const float* Qp = (const float*)d_in[1];
    const float* Kp = (const float*)d_in[2];
    const float* Vp = (const float*)d_in[3];
    const int*   pm = (const int*)d_in[4];
    float* out = (float*)d_out;

    proj_kernel  <<<dim3(kT / 64, kN / 128, 48), 256>>>(x, Qp, Kp, Vp);
    scores_kernel<<<dim3(kN / 64, kN / 64, kCB), 256>>>(pm);
    maxsum_kernel<<<kNN / 256, 256>>>();
    ctx_kernel   <<<dim3(kN / 128, kCB), 256>>>(out);
    if (out_size >= kOUTSZ + kATTSZ) {
        attn_kernel<<<kATTSZ / 256, 256>>>(out);
    }
}